// round 16
// baseline (speedup 1.0000x reference)
#include <cuda_runtime.h>
#include <math.h>

#define BTOT   65536
#define INS    360
#define L1N    180
#define NPOS   90
#define TS     32
#define KIN    33
#define HID    24
#define NSAMP  128         // samples per block
#define THREADS 256

// ---- shared memory layout (float offsets) ----
#define OFF_W1F   0        // 30
#define OFF_B1F   30       // 6
#define OFF_W2F   36       // 216
#define OFF_B2F   252      // 12
#define OFF_WIH   264      // 96 x 36
#define OFF_WHH   3720     // 96 x 28
#define OFF_BSUM  6408     // 96
#define OFF_RTW1  6504     // 432
#define OFF_RTB1  6936     // 12
#define OFF_RTW2  6948     // 24
#define OFF_RTB2  6972     // 4
#define OFF_FUSW  6976     // 864
#define OFF_FUSB  7840     // 24
#define OFF_CW1   7864     // 288
#define OFF_CB1   8152     // 12
#define OFF_CW2   8164     // 60
#define OFF_CB2   8224     // 8
#define OFF_SA    8232     // 12 x 128
#define OFF_MLO   9768     // uint[32][128]
#define OFF_MHI   13864    // uint[128]
#define OFF_HS    13992    // 128 x 28 (sample-major h)
#define OFF_CS    17576    // 24 x 132 (unit-major c)
#define OFF_SCR   20744    // 8 warps x 580 (16-row conv chunks)
#define SCRSTR    580
#define SMEM_FLOATS 25384
#define SMEM_BYTES  (SMEM_FLOATS * 4)   // 101536

__device__ __forceinline__ float sigf(float x) {
    return __fdividef(1.0f, 1.0f + __expf(-x));
}
__device__ __forceinline__ float tanhfast(float x) {
    return fmaf(2.0f, __fdividef(1.0f, 1.0f + __expf(-2.0f * x)), -1.0f);
}

__global__ __launch_bounds__(THREADS, 2) void fused_kernel(
    const float* __restrict__ x,
    const float* __restrict__ c1w, const float* __restrict__ c1b,
    const float* __restrict__ bn1g, const float* __restrict__ bn1b,
    const float* __restrict__ bn1m, const float* __restrict__ bn1v,
    const float* __restrict__ c2w, const float* __restrict__ c2b,
    const float* __restrict__ bn2g, const float* __restrict__ bn2b,
    const float* __restrict__ bn2m, const float* __restrict__ bn2v,
    const float* __restrict__ wih, const float* __restrict__ whh,
    const float* __restrict__ bih, const float* __restrict__ bhh,
    const float* __restrict__ rtw1, const float* __restrict__ rtb1,
    const float* __restrict__ rtw2, const float* __restrict__ rtb2,
    const float* __restrict__ fusw, const float* __restrict__ fusb,
    const float* __restrict__ cw1, const float* __restrict__ cb1,
    const float* __restrict__ cw2, const float* __restrict__ cb2,
    float* __restrict__ out)
{
    extern __shared__ float sm[];
    const int tid  = threadIdx.x;
    const int wid  = tid >> 5;
    const int lane = tid & 31;

    // ---------------- init: fold BN + stage weights ----------------
    if (tid < 6) {
        float sc = bn1g[tid] * rsqrtf(bn1v[tid] + 1e-5f);
        #pragma unroll
        for (int r = 0; r < 5; r++) sm[OFF_W1F + tid * 5 + r] = c1w[tid * 5 + r] * sc;
        sm[OFF_B1F + tid] = (c1b[tid] - bn1m[tid]) * sc + bn1b[tid];
    } else if (tid >= 32 && tid < 44) {
        int co = tid - 32;
        float sc = bn2g[co] * rsqrtf(bn2v[co] + 1e-5f);
        #pragma unroll
        for (int i = 0; i < 18; i++) sm[OFF_W2F + co * 18 + i] = c2w[co * 18 + i] * sc;
        sm[OFF_B2F + co] = (c2b[co] - bn2m[co]) * sc + bn2b[co];
    }
    for (int i = tid; i < 96 * KIN; i += THREADS) {
        int r = i / KIN, k = i - r * KIN;
        sm[OFF_WIH + r * 36 + k] = wih[i];
    }
    for (int i = tid; i < 96 * HID; i += THREADS) {
        int r = i / HID, k = i - r * HID;
        sm[OFF_WHH + r * 28 + k] = whh[i];
    }
    if (tid < 96) sm[OFF_BSUM + tid] = bih[tid] + bhh[tid];
    for (int i = tid; i < 432; i += THREADS) sm[OFF_RTW1 + i] = rtw1[i];
    for (int i = tid; i < 864; i += THREADS) sm[OFF_FUSW + i] = fusw[i];
    for (int i = tid; i < 288; i += THREADS) sm[OFF_CW1 + i] = cw1[i];
    if (tid < 12) sm[OFF_RTB1 + tid] = rtb1[tid];
    if (tid < 24) sm[OFF_RTW2 + tid] = rtw2[tid];
    if (tid < 2)  sm[OFF_RTB2 + tid] = rtb2[tid];
    if (tid < 24) sm[OFF_FUSB + tid] = fusb[tid];
    if (tid < 12) sm[OFF_CB1 + tid] = cb1[tid];
    if (tid < 60) sm[OFF_CW2 + tid] = cw2[tid];
    if (tid < 5)  sm[OFF_CB2 + tid] = cb2[tid];
    for (int i = tid; i < 12 * NSAMP; i += THREADS) sm[OFF_SA + i] = 0.0f;
    for (int i = tid; i < NSAMP * 28; i += THREADS) sm[OFF_HS + i] = 0.0f;
    for (int i = tid; i < 24 * 132; i += THREADS) sm[OFF_CS + i] = 0.0f;
    __syncthreads();

    unsigned* mlo = (unsigned*)(sm + OFF_MLO);
    unsigned* mhi = (unsigned*)(sm + OFF_MHI);

    // ---------------- conv + LIF: 8 warps, warp owns 16 samples (verbatim) ----------------
    {
        float* scratch = sm + OFF_SCR + wid * SCRSTR;   // 16 rows x 36
        #pragma unroll 1
        for (int ss = 0; ss < 16; ss++) {
            const int s_blk = wid * 16 + ss;
            const float* xr = x + (size_t)(blockIdx.x * NSAMP + s_blk) * INS;

            float sacc[12];
            #pragma unroll
            for (int co = 0; co < 12; co++) sacc[co] = 0.0f;
            float m1a = 0.0f, m2a = 0.0f, m1b = 0.0f, m2b = 0.0f;
            unsigned hib = 0;

            #pragma unroll 1
            for (int chunk = 0; chunk < 2; chunk++) {
                const int plim = (chunk == 0) ? 44 : 46;
                #pragma unroll 1
                for (int it = 0; it < 2; it++) {
                    int p_local = it * 32 + lane;
                    if (p_local < plim) {
                        int p = chunk * 44 + p_local;
                        float c1v[3][6];
                        #pragma unroll
                        for (int dq = 0; dq < 3; dq++) {
                            int q = 2 * p - 1 + dq;
                            if (q >= 0 && q < L1N) {
                                int base = 2 * q - 2;
                                #pragma unroll
                                for (int ci = 0; ci < 6; ci++) {
                                    float acc = sm[OFF_B1F + ci];
                                    #pragma unroll
                                    for (int rr = 0; rr < 5; rr++) {
                                        int idx = base + rr;
                                        if (idx >= 0 && idx < INS)
                                            acc = fmaf(sm[OFF_W1F + ci * 5 + rr], xr[idx], acc);
                                    }
                                    c1v[dq][ci] = fmaxf(acc, 0.0f);
                                }
                            } else {
                                #pragma unroll
                                for (int ci = 0; ci < 6; ci++) c1v[dq][ci] = 0.0f;
                            }
                        }
                        int f0 = p * 12;
                        int t  = f0 / 33;
                        int k  = f0 - t * 33;
                        bool store = (p < 88);
                        int trel = t - chunk * 16;
                        #pragma unroll
                        for (int co = 0; co < 12; co++) {
                            float acc = sm[OFF_B2F + co];
                            #pragma unroll
                            for (int dq = 0; dq < 3; dq++)
                                #pragma unroll
                                for (int ci = 0; ci < 6; ci++)
                                    acc = fmaf(sm[OFF_W2F + (co * 6 + ci) * 3 + dq], c1v[dq][ci], acc);
                            float v = fmaxf(acc, 0.0f);
                            sacc[co] += v;
                            if (store) scratch[trel * 36 + k] = v;
                            if (++k == 33) { k = 0; ++trel; }
                        }
                    }
                }
                __syncwarp();
                #pragma unroll 1
                for (int tr = 0; tr < 16; tr++) {
                    const float* row = scratch + tr * 36;
                    float xv = row[lane];
                    float m1 = fmaf(0.95f, m1a, xv);
                    bool f1 = (m1 > 0.5f);
                    m1a = f1 ? 0.0f : m1;
                    float m2 = fmaf(0.9f, m2a, f1 ? 1.0f : 0.0f);
                    bool f2 = (m2 > 0.6f);
                    m2a = f2 ? 0.0f : m2;
                    unsigned lo = __ballot_sync(0xffffffffu, f2);
                    if (lane == 0) {
                        float xb = row[32];
                        float n1 = fmaf(0.95f, m1b, xb);
                        bool g1 = (n1 > 0.5f);
                        m1b = g1 ? 0.0f : n1;
                        float n2 = fmaf(0.9f, m2b, g1 ? 1.0f : 0.0f);
                        bool g2 = (n2 > 0.6f);
                        m2b = g2 ? 0.0f : n2;
                        int tg = chunk * 16 + tr;
                        mlo[tg * NSAMP + s_blk] = lo;
                        if (g2) hib |= (1u << tg);
                    }
                }
                __syncwarp();
            }
            #pragma unroll
            for (int co = 0; co < 12; co++)
                atomicAdd(&sm[OFF_SA + co * NSAMP + s_blk], sacc[co]);
            if (lane == 0) mhi[s_blk] = hib;
        }
    }
    __syncthreads();   // masks/SA/HS/CS visible to all

    // ---------------- LSTM: tid<128; thread = (pair, half) -> 12 units x 2 samples ----------
    if (tid < 128) {
        const int s0   = tid & ~1;          // even sample of pair
        const int half = tid & 1;
        const int u0   = half * 12;
        const uint2 hb = *(const uint2*)&mhi[s0];
        float* hs0 = sm + OFF_HS + s0 * 28;
        float* hs1 = hs0 + 28;
        float* cs  = sm + OFF_CS;

        #pragma unroll 1
        for (int t = 0; t < TS; t++) {
            __syncwarp();   // prev-step h writes visible
            uint2 ml = *(const uint2*)&mlo[t * NSAMP + s0];
            float sp0[KIN], sp1[KIN];
            #pragma unroll
            for (int k = 0; k < 32; k++) {
                sp0[k] = (ml.x & (1u << k)) ? 1.0f : 0.0f;
                sp1[k] = (ml.y & (1u << k)) ? 1.0f : 0.0f;
            }
            sp0[32] = ((hb.x >> t) & 1u) ? 1.0f : 0.0f;
            sp1[32] = ((hb.y >> t) & 1u) ? 1.0f : 0.0f;

            float4 hv0[6], hv1[6];
            #pragma unroll
            for (int j = 0; j < 6; j++) {
                hv0[j] = ((const float4*)hs0)[j];
                hv1[j] = ((const float4*)hs1)[j];
            }
            __syncwarp();   // all reads done before anyone writes step-t h

            #pragma unroll 2
            for (int u = 0; u < 12; u++) {
                const int ua = u0 + u;
                const float* wi = sm + OFF_WIH + ua * 36;
                const float* wf = wi + 24 * 36;
                const float* wg = wi + 48 * 36;
                const float* wo = wi + 72 * 36;
                float gi0 = sm[OFF_BSUM + ua];
                float gf0 = sm[OFF_BSUM + 24 + ua];
                float gg0 = sm[OFF_BSUM + 48 + ua];
                float go0 = sm[OFF_BSUM + 72 + ua];
                float gi1 = gi0, gf1 = gf0, gg1 = gg0, go1 = go0;
                #pragma unroll
                for (int i2 = 0; i2 < 8; i2++) {
                    float4 qi = ((const float4*)wi)[i2];
                    float4 qf = ((const float4*)wf)[i2];
                    float4 qg = ((const float4*)wg)[i2];
                    float4 qo = ((const float4*)wo)[i2];
                    float a0 = sp0[4 * i2],     b0 = sp1[4 * i2];
                    float a1 = sp0[4 * i2 + 1], b1 = sp1[4 * i2 + 1];
                    float a2 = sp0[4 * i2 + 2], b2 = sp1[4 * i2 + 2];
                    float a3 = sp0[4 * i2 + 3], b3 = sp1[4 * i2 + 3];
                    gi0 = fmaf(qi.x, a0, gi0); gi1 = fmaf(qi.x, b0, gi1);
                    gi0 = fmaf(qi.y, a1, gi0); gi1 = fmaf(qi.y, b1, gi1);
                    gi0 = fmaf(qi.z, a2, gi0); gi1 = fmaf(qi.z, b2, gi1);
                    gi0 = fmaf(qi.w, a3, gi0); gi1 = fmaf(qi.w, b3, gi1);
                    gf0 = fmaf(qf.x, a0, gf0); gf1 = fmaf(qf.x, b0, gf1);
                    gf0 = fmaf(qf.y, a1, gf0); gf1 = fmaf(qf.y, b1, gf1);
                    gf0 = fmaf(qf.z, a2, gf0); gf1 = fmaf(qf.z, b2, gf1);
                    gf0 = fmaf(qf.w, a3, gf0); gf1 = fmaf(qf.w, b3, gf1);
                    gg0 = fmaf(qg.x, a0, gg0); gg1 = fmaf(qg.x, b0, gg1);
                    gg0 = fmaf(qg.y, a1, gg0); gg1 = fmaf(qg.y, b1, gg1);
                    gg0 = fmaf(qg.z, a2, gg0); gg1 = fmaf(qg.z, b2, gg1);
                    gg0 = fmaf(qg.w, a3, gg0); gg1 = fmaf(qg.w, b3, gg1);
                    go0 = fmaf(qo.x, a0, go0); go1 = fmaf(qo.x, b0, go1);
                    go0 = fmaf(qo.y, a1, go0); go1 = fmaf(qo.y, b1, go1);
                    go0 = fmaf(qo.z, a2, go0); go1 = fmaf(qo.z, b2, go1);
                    go0 = fmaf(qo.w, a3, go0); go1 = fmaf(qo.w, b3, go1);
                }
                float wl;
                wl = wi[32]; gi0 = fmaf(wl, sp0[32], gi0); gi1 = fmaf(wl, sp1[32], gi1);
                wl = wf[32]; gf0 = fmaf(wl, sp0[32], gf0); gf1 = fmaf(wl, sp1[32], gf1);
                wl = wg[32]; gg0 = fmaf(wl, sp0[32], gg0); gg1 = fmaf(wl, sp1[32], gg1);
                wl = wo[32]; go0 = fmaf(wl, sp0[32], go0); go1 = fmaf(wl, sp1[32], go1);
                const float* vi = sm + OFF_WHH + ua * 28;
                const float* vf = vi + 24 * 28;
                const float* vg = vi + 48 * 28;
                const float* vo = vi + 72 * 28;
                #pragma unroll
                for (int j2 = 0; j2 < 6; j2++) {
                    float4 qi = ((const float4*)vi)[j2];
                    float4 qf = ((const float4*)vf)[j2];
                    float4 qg = ((const float4*)vg)[j2];
                    float4 qo = ((const float4*)vo)[j2];
                    float a0 = hv0[j2].x, b0 = hv1[j2].x;
                    float a1 = hv0[j2].y, b1 = hv1[j2].y;
                    float a2 = hv0[j2].z, b2 = hv1[j2].z;
                    float a3 = hv0[j2].w, b3 = hv1[j2].w;
                    gi0 = fmaf(qi.x, a0, gi0); gi1 = fmaf(qi.x, b0, gi1);
                    gi0 = fmaf(qi.y, a1, gi0); gi1 = fmaf(qi.y, b1, gi1);
                    gi0 = fmaf(qi.z, a2, gi0); gi1 = fmaf(qi.z, b2, gi1);
                    gi0 = fmaf(qi.w, a3, gi0); gi1 = fmaf(qi.w, b3, gi1);
                    gf0 = fmaf(qf.x, a0, gf0); gf1 = fmaf(qf.x, b0, gf1);
                    gf0 = fmaf(qf.y, a1, gf0); gf1 = fmaf(qf.y, b1, gf1);
                    gf0 = fmaf(qf.z, a2, gf0); gf1 = fmaf(qf.z, b2, gf1);
                    gf0 = fmaf(qf.w, a3, gf0); gf1 = fmaf(qf.w, b3, gf1);
                    gg0 = fmaf(qg.x, a0, gg0); gg1 = fmaf(qg.x, b0, gg1);
                    gg0 = fmaf(qg.y, a1, gg0); gg1 = fmaf(qg.y, b1, gg1);
                    gg0 = fmaf(qg.z, a2, gg0); gg1 = fmaf(qg.z, b2, gg1);
                    gg0 = fmaf(qg.w, a3, gg0); gg1 = fmaf(qg.w, b3, gg1);
                    go0 = fmaf(qo.x, a0, go0); go1 = fmaf(qo.x, b0, go1);
                    go0 = fmaf(qo.y, a1, go0); go1 = fmaf(qo.y, b1, go1);
                    go0 = fmaf(qo.z, a2, go0); go1 = fmaf(qo.z, b2, go1);
                    go0 = fmaf(qo.w, a3, go0); go1 = fmaf(qo.w, b3, go1);
                }
                float cc0 = cs[ua * 132 + s0];
                float cc1 = cs[ua * 132 + s0 + 1];
                cc0 = fmaf(sigf(gf0), cc0, sigf(gi0) * tanhfast(gg0));
                cc1 = fmaf(sigf(gf1), cc1, sigf(gi1) * tanhfast(gg1));
                cs[ua * 132 + s0]     = cc0;
                cs[ua * 132 + s0 + 1] = cc1;
                hs0[ua] = sigf(go0) * tanhfast(cc0);
                hs1[ua] = sigf(go1) * tanhfast(cc1);
            }
        }
        __syncwarp();

        // ---------------- head: thread = sample (sample index == tid) ----------------
        {
            const int s = tid;
            const float* hsx = sm + OFF_HS + s * 28;
            float h[HID];
            #pragma unroll
            for (int j = 0; j < 6; j++) {
                float4 q = ((const float4*)hsx)[j];
                h[4 * j] = q.x; h[4 * j + 1] = q.y; h[4 * j + 2] = q.z; h[4 * j + 3] = q.w;
            }
            float sa[12];
            #pragma unroll
            for (int ch = 0; ch < 12; ch++) sa[ch] = sm[OFF_SA + ch * NSAMP + s] * (1.0f / 90.0f);

            float a1[12];
            #pragma unroll
            for (int i = 0; i < 12; i++) {
                float acc = sm[OFF_RTB1 + i];
                #pragma unroll
                for (int j = 0; j < 24; j++) acc = fmaf(sm[OFF_RTW1 + i * 36 + j], h[j], acc);
                #pragma unroll
                for (int j = 0; j < 12; j++) acc = fmaf(sm[OFF_RTW1 + i * 36 + 24 + j], sa[j], acc);
                a1[i] = fmaxf(acc, 0.0f);
            }
            float l0 = sm[OFF_RTB2 + 0], l1 = sm[OFF_RTB2 + 1];
            #pragma unroll
            for (int j = 0; j < 12; j++) {
                l0 = fmaf(sm[OFF_RTW2 + j], a1[j], l0);
                l1 = fmaf(sm[OFF_RTW2 + 12 + j], a1[j], l1);
            }
            float mx = fmaxf(l0, l1);
            float e0 = __expf(l0 - mx), e1 = __expf(l1 - mx);
            float inv = 1.0f / (e0 + e1);
            float r0 = 0.7f * e0 * inv, r1 = 0.3f * e1 * inv;
            float alpha = r0 / (r0 + r1);
            float beta  = 1.0f - alpha;

            float fused[24];
            #pragma unroll
            for (int o = 0; o < 24; o++) {
                float acc = sm[OFF_FUSB + o];
                #pragma unroll
                for (int j = 0; j < 24; j++) acc = fmaf(sm[OFF_FUSW + o * 36 + j], h[j] * alpha, acc);
                #pragma unroll
                for (int j = 0; j < 12; j++) acc = fmaf(sm[OFF_FUSW + o * 36 + 24 + j], sa[j] * beta, acc);
                fused[o] = fmaxf(acc, 0.0f);
            }
            float z[12];
            #pragma unroll
            for (int i = 0; i < 12; i++) {
                float acc = sm[OFF_CB1 + i];
                #pragma unroll
                for (int o = 0; o < 24; o++) acc = fmaf(sm[OFF_CW1 + i * 24 + o], fused[o], acc);
                z[i] = fmaxf(acc, 0.0f);
            }
            #pragma unroll
            for (int o = 0; o < 5; o++) {
                float acc = sm[OFF_CB2 + o];
                #pragma unroll
                for (int i = 0; i < 12; i++) acc = fmaf(sm[OFF_CW2 + o * 12 + i], z[i], acc);
                out[(size_t)(blockIdx.x * NSAMP + s) * 5 + o] = acc;
            }
        }
    }
}

// =====================================================================
extern "C" void kernel_launch(void* const* d_in, const int* in_sizes, int n_in,
                              void* d_out, int out_size) {
    (void)in_sizes; (void)n_in; (void)out_size;
    cudaFuncSetAttribute(fused_kernel,
                         cudaFuncAttributeMaxDynamicSharedMemorySize, SMEM_BYTES);
    fused_kernel<<<BTOT / NSAMP, THREADS, SMEM_BYTES>>>(
        (const float*)d_in[0],
        (const float*)d_in[1],  (const float*)d_in[2],
        (const float*)d_in[3],  (const float*)d_in[4],
        (const float*)d_in[5],  (const float*)d_in[6],
        (const float*)d_in[7],  (const float*)d_in[8],
        (const float*)d_in[9],  (const float*)d_in[10],
        (const float*)d_in[11], (const float*)d_in[12],
        (const float*)d_in[13], (const float*)d_in[14],
        (const float*)d_in[15], (const float*)d_in[16],
        (const float*)d_in[17], (const float*)d_in[18],
        (const float*)d_in[19], (const float*)d_in[20],
        (const float*)d_in[21], (const float*)d_in[22],
        (const float*)d_in[23], (const float*)d_in[24],
        (const float*)d_in[25], (const float*)d_in[26],
        (float*)d_out);
}